// round 12
// baseline (speedup 1.0000x reference)
#include <cuda_runtime.h>
#include <cuda_bf16.h>
#include <mma.h>
#include <stdint.h>

using namespace nvcuda;

#define NMAX 100000
#define NPAD 100032        // NMAX rounded up to 64 (whole-tile stores at tail)
#define EMAX 1600000
#define FT   128           // in_ft == out_ft == 128

// ---------------- device scratch (allocation-free) ----------------
__device__ float         g_fts[NPAD * FT]; // linear transform result [N,128]
__device__ __nv_bfloat16 g_Whi[FT * FT];   // W hi bf16
__device__ __nv_bfloat16 g_Wlo[FT * FT];   // W residual bf16
__device__ int   g_deg[NMAX];              // per-dst degree (zero-init; re-zeroed by scatter)
__device__ int   g_off[NMAX + 1];          // CSR offsets
__device__ int   g_pos[NMAX];              // scatter cursors
__device__ int2  g_edge[EMAX];             // dst-grouped {src, val_bits}
__device__ int   g_part[512];              // scan partials

// ---------------- 0) split W into bf16 hi/lo ----------------
__global__ void w_split_kernel(const float* __restrict__ W)
{
    int i = blockIdx.x * blockDim.x + threadIdx.x;
    if (i < FT * FT) {
        float w = W[i];
        __nv_bfloat16 hi = __float2bfloat16(w);
        float lo = w - __bfloat162float(hi);
        g_Whi[i] = hi;
        g_Wlo[i] = __float2bfloat16(lo);
    }
}

// ---------------- 1) GEMM: fts = seq @ W^T via WMMA bf16-split -------------
// block = 256 threads (8 warps), 64 rows x 128 cols.
// smem: Whi/Wlo (full W, 64KB) staged ONCE per block + A hi/lo (32KB) = 96KB.
// Warp grid 2x4: warp computes a square 32x32 output tile (4 acc fragments);
// all fragment loads are smem-side (LDS), none from global.
// D = Ah*Bh + Ah*Bl + Al*Bh with fp32 accumulation (AlBl dropped, ~2^-18 rel).
__global__ void __launch_bounds__(256)
gemm_wmma_kernel(const float* __restrict__ seq, int n)
{
    extern __shared__ char smx[];
    __nv_bfloat16* Whi_s = (__nv_bfloat16*)smx;       // 128*128 bf16 = 32KB
    __nv_bfloat16* Wlo_s = Whi_s + FT * FT;           // 32KB
    __nv_bfloat16* Ahi   = Wlo_s + FT * FT;           // 64*128 bf16 = 16KB
    __nv_bfloat16* Alo   = Ahi + 64 * FT;             // 16KB

    const int tid = threadIdx.x;
    const int wid = tid >> 5;
    const int rowBase = blockIdx.x * 64;

    // stage W hi/lo into smem (2048 int4 each; coalesced, L2-hot)
    {
        const int4* srcH = (const int4*)g_Whi;
        const int4* srcL = (const int4*)g_Wlo;
        int4* dstH = (int4*)Whi_s;
        int4* dstL = (int4*)Wlo_s;
        for (int i = tid; i < FT * FT / 8; i += 256) {
            dstH[i] = srcH[i];
            dstL[i] = srcL[i];
        }
    }

    // convert 64 seq rows to bf16 hi/lo in smem (2048 float4, 8 per thread)
    for (int i = tid; i < 64 * 32; i += 256) {
        int row = i >> 5;
        int c4  = i & 31;
        float4 v = make_float4(0.f, 0.f, 0.f, 0.f);
        int grow = rowBase + row;
        if (grow < n)
            v = ((const float4*)(seq + (size_t)grow * FT))[c4];
        __nv_bfloat16 h0 = __float2bfloat16(v.x);
        __nv_bfloat16 h1 = __float2bfloat16(v.y);
        __nv_bfloat16 h2 = __float2bfloat16(v.z);
        __nv_bfloat16 h3 = __float2bfloat16(v.w);
        __nv_bfloat162* dh = (__nv_bfloat162*)(Ahi + row * FT + c4 * 4);
        dh[0] = __nv_bfloat162(h0, h1);
        dh[1] = __nv_bfloat162(h2, h3);
        __nv_bfloat162* dl = (__nv_bfloat162*)(Alo + row * FT + c4 * 4);
        dl[0] = __nv_bfloat162(__float2bfloat16(v.x - __bfloat162float(h0)),
                               __float2bfloat16(v.y - __bfloat162float(h1)));
        dl[1] = __nv_bfloat162(__float2bfloat16(v.z - __bfloat162float(h2)),
                               __float2bfloat16(v.w - __bfloat162float(h3)));
    }
    __syncthreads();

    const int mrow = (wid & 1) * 32;          // warp row group (0 or 32)
    const int colB = (wid >> 1) * 32;         // warp col group (0..96)

    wmma::fragment<wmma::accumulator, 16, 16, 16, float> acc[2][2];
#pragma unroll
    for (int mr = 0; mr < 2; mr++)
#pragma unroll
        for (int mc = 0; mc < 2; mc++)
            wmma::fill_fragment(acc[mr][mc], 0.0f);

#pragma unroll
    for (int kt = 0; kt < 8; kt++) {
        const int k = kt * 16;
        wmma::fragment<wmma::matrix_a, 16, 16, 16, __nv_bfloat16, wmma::row_major> ah[2], al[2];
#pragma unroll
        for (int mr = 0; mr < 2; mr++) {
            wmma::load_matrix_sync(ah[mr], Ahi + (mrow + mr * 16) * FT + k, FT);
            wmma::load_matrix_sync(al[mr], Alo + (mrow + mr * 16) * FT + k, FT);
        }
#pragma unroll
        for (int mc = 0; mc < 2; mc++) {
            const int col = colB + mc * 16;
            wmma::fragment<wmma::matrix_b, 16, 16, 16, __nv_bfloat16, wmma::col_major> bh, bl;
            wmma::load_matrix_sync(bh, Whi_s + (size_t)col * FT + k, FT);
            wmma::load_matrix_sync(bl, Wlo_s + (size_t)col * FT + k, FT);
#pragma unroll
            for (int mr = 0; mr < 2; mr++) {
                wmma::mma_sync(acc[mr][mc], ah[mr], bh, acc[mr][mc]);
                wmma::mma_sync(acc[mr][mc], ah[mr], bl, acc[mr][mc]);
                wmma::mma_sync(acc[mr][mc], al[mr], bh, acc[mr][mc]);
            }
        }
    }

#pragma unroll
    for (int mr = 0; mr < 2; mr++)
#pragma unroll
        for (int mc = 0; mc < 2; mc++) {
            float* dst = g_fts + (size_t)(rowBase + mrow + mr * 16) * FT
                       + colB + mc * 16;
            wmma::store_matrix_sync(dst, acc[mr][mc], FT, wmma::mem_row_major);
        }
}

// ---------------- 2) histogram of dst (4 edges/thread, vector loads) -------
__global__ void hist_kernel(const int* __restrict__ dst, int e)
{
    int i4 = (blockIdx.x * blockDim.x + threadIdx.x) * 4;
    if (i4 + 3 < e) {
        int4 d = *(const int4*)(dst + i4);
        atomicAdd(&g_deg[d.x], 1);
        atomicAdd(&g_deg[d.y], 1);
        atomicAdd(&g_deg[d.z], 1);
        atomicAdd(&g_deg[d.w], 1);
    } else {
        for (int i = i4; i < e; i++) atomicAdd(&g_deg[dst[i]], 1);
    }
}

// ---------------- 3) scan: per-chunk partial sums ----------------
__global__ void scan_partials(int n)
{
    __shared__ int s[256];
    int i = blockIdx.x * 256 + threadIdx.x;
    int v = (i < n) ? g_deg[i] : 0;
    s[threadIdx.x] = v;
    __syncthreads();
    for (int d = 128; d > 0; d >>= 1) {
        if (threadIdx.x < d) s[threadIdx.x] += s[threadIdx.x + d];
        __syncthreads();
    }
    if (threadIdx.x == 0) g_part[blockIdx.x] = s[0];
}

// ---------------- 4) scan: write offsets (computes own chunk prefix) -------
__global__ void scan_write(int n, int nchunks)
{
    __shared__ int s[256];
    __shared__ int base_sh;
    const int t = threadIdx.x;
    const int b = blockIdx.x;

    {
        int acc = 0;
        for (int c = t; c < b; c += 256) acc += g_part[c];
        s[t] = acc;
        __syncthreads();
        for (int d = 128; d > 0; d >>= 1) {
            if (t < d) s[t] += s[t + d];
            __syncthreads();
        }
        if (t == 0) base_sh = s[0];
        __syncthreads();
    }
    const int base = base_sh;
    __syncthreads();

    int i = b * 256 + t;
    int v = (i < n) ? g_deg[i] : 0;
    s[t] = v;
    __syncthreads();
    for (int d = 1; d < 256; d <<= 1) {
        int tmp = (t >= d) ? s[t - d] : 0;
        __syncthreads();
        s[t] += tmp;
        __syncthreads();
    }
    int incl = s[t];
    int excl = incl - v;
    if (i < n) {
        int off = base + excl;
        g_off[i] = off;
        g_pos[i] = off;
    }
    if (b == nchunks - 1 && t == 255)
        g_off[n] = base + incl;
}

// ---------------- 5) scatter (4 edges/thread) + re-zero g_deg --------------
__global__ void scatter_kernel(const int*   __restrict__ dst,
                               const int*   __restrict__ src,
                               const float* __restrict__ val,
                               int e, int n)
{
    int tidg = blockIdx.x * blockDim.x + threadIdx.x;
    int i4 = tidg * 4;
    if (i4 + 3 < e) {
        int4   d = *(const int4*)  (dst + i4);
        int4   s = *(const int4*)  (src + i4);
        float4 v = *(const float4*)(val + i4);
        int p0 = atomicAdd(&g_pos[d.x], 1);
        int p1 = atomicAdd(&g_pos[d.y], 1);
        int p2 = atomicAdd(&g_pos[d.z], 1);
        int p3 = atomicAdd(&g_pos[d.w], 1);
        g_edge[p0] = make_int2(s.x, __float_as_int(v.x));
        g_edge[p1] = make_int2(s.y, __float_as_int(v.y));
        g_edge[p2] = make_int2(s.z, __float_as_int(v.z));
        g_edge[p3] = make_int2(s.w, __float_as_int(v.w));
    } else {
        for (int i = i4; i < e; i++) {
            int idx = atomicAdd(&g_pos[dst[i]], 1);
            g_edge[idx] = make_int2(src[i], __float_as_int(val[i]));
        }
    }
    // g_deg is dead after scan_write; reset 4 entries per thread for the
    // next replay (no separate memset launch).
    if (i4 < n) {
        int lim = min(i4 + 4, n);
        for (int i = i4; i < lim; i++) g_deg[i] = 0;
    }
}

// ---------------- 6) SpMM gather: warp per dst node, no float atomics ------
__global__ void spmm_kernel(const float* __restrict__ bias,
                            const float* __restrict__ prelu_a,
                            float* __restrict__ out,
                            int n)
{
    const int warp = (blockIdx.x * blockDim.x + threadIdx.x) >> 5;
    const int lane = threadIdx.x & 31;
    if (warp >= n) return;

    const int off0 = g_off[warp];
    const int off1 = g_off[warp + 1];

    float4 acc = make_float4(0.f, 0.f, 0.f, 0.f);
    const float4* fts4 = (const float4*)g_fts;

    for (int base = off0; base < off1; base += 32) {
        int e = base + lane;
        int   s = 0;
        float v = 0.f;
        if (e < off1) {
            int2 p = __ldcs(&g_edge[e]);   // coalesced 8B read, evict-first
            s = p.x;
            v = __int_as_float(p.y);
        }
        int cnt = min(32, off1 - base);
#pragma unroll 8
        for (int j = 0; j < cnt; j++) {
            int   sj = __shfl_sync(0xffffffffu, s, j);
            float vj = __shfl_sync(0xffffffffu, v, j);
            float4 f = fts4[(size_t)sj * 32 + lane];
            acc.x += vj * f.x;
            acc.y += vj * f.y;
            acc.z += vj * f.z;
            acc.w += vj * f.w;
        }
    }

    float4 b4 = ((const float4*)bias)[lane];
    float  a  = prelu_a[0];
    float4 o;
    o.x = acc.x + b4.x; o.y = acc.y + b4.y;
    o.z = acc.z + b4.z; o.w = acc.w + b4.w;
    o.x = (o.x >= 0.f) ? o.x : a * o.x;
    o.y = (o.y >= 0.f) ? o.y : a * o.y;
    o.z = (o.z >= 0.f) ? o.z : a * o.z;
    o.w = (o.w >= 0.f) ? o.w : a * o.w;
    __stcs((float4*)(out + (size_t)warp * FT) + lane, o);  // evict-first write
}

// ---------------- side-stream handles (created at program load) ------------
struct AuxStreams {
    cudaStream_t s2;
    cudaEvent_t  evFork, evJoin;
    AuxStreams() {
        cudaStreamCreateWithFlags(&s2, cudaStreamNonBlocking);
        cudaEventCreateWithFlags(&evFork, cudaEventDisableTiming);
        cudaEventCreateWithFlags(&evJoin, cudaEventDisableTiming);
    }
};
static AuxStreams g_aux;

// ---------------- launcher ----------------
extern "C" void kernel_launch(void* const* d_in, const int* in_sizes, int n_in,
                              void* d_out, int out_size)
{
    const float* seq      = (const float*)d_in[0];
    const float* W        = (const float*)d_in[1];
    const float* bias     = (const float*)d_in[2];
    const float* prelu_a  = (const float*)d_in[3];
    const float* edge_val = (const float*)d_in[4];
    const int*   edge_src = (const int*)  d_in[5];
    const int*   edge_dst = (const int*)  d_in[6];

    const int n = in_sizes[0] / FT;     // 100000
    const int e = in_sizes[4];          // 1600000

    // fork: branch B (CSR build) runs on side stream s2
    cudaEventRecord(g_aux.evFork, 0);
    cudaStreamWaitEvent(g_aux.s2, g_aux.evFork, 0);

    // ----- branch B: CSR build on s2 -----
    const int e4blocks = (e / 4 + 255) / 256 + 1;
    hist_kernel<<<e4blocks, 256, 0, g_aux.s2>>>(edge_dst, e);
    const int nchunks = (n + 255) / 256;
    scan_partials<<<nchunks, 256, 0, g_aux.s2>>>(n);
    scan_write<<<nchunks, 256, 0, g_aux.s2>>>(n, nchunks);
    scatter_kernel<<<e4blocks, 256, 0, g_aux.s2>>>(edge_dst, edge_src, edge_val, e, n);
    cudaEventRecord(g_aux.evJoin, g_aux.s2);

    // ----- branch A: WMMA bf16-split GEMM (smem-staged W) on default stream --
    w_split_kernel<<<(FT * FT + 255) / 256, 256>>>(W);
    const int gemm_smem = (2 * FT * FT + 2 * 64 * FT) * sizeof(__nv_bfloat16); // 96KB
    cudaFuncSetAttribute(gemm_wmma_kernel,
                         cudaFuncAttributeMaxDynamicSharedMemorySize, gemm_smem);
    gemm_wmma_kernel<<<(n + 63) / 64, 256, gemm_smem>>>(seq, n);

    // join, then SpMM (needs both branches)
    cudaStreamWaitEvent(0, g_aux.evJoin, 0);
    const int warps_per_block = 8;
    spmm_kernel<<<(n + warps_per_block - 1) / warps_per_block, warps_per_block * 32>>>(
        bias, prelu_a, (float*)d_out, n);
}

// round 13
// speedup vs baseline: 1.4129x; 1.4129x over previous
#include <cuda_runtime.h>
#include <cuda_bf16.h>
#include <mma.h>
#include <stdint.h>

using namespace nvcuda;

#define NMAX 100000
#define NPAD 100032        // NMAX rounded up to 64 (whole-tile stores at tail)
#define EMAX 1600000
#define FT   128           // in_ft == out_ft == 128

// ---------------- device scratch (allocation-free) ----------------
__device__ float         g_fts[NPAD * FT]; // linear transform result [N,128]
__device__ __nv_bfloat16 g_Whi[FT * FT];   // W hi bf16
__device__ __nv_bfloat16 g_Wlo[FT * FT];   // W residual bf16
__device__ int   g_deg[NMAX];              // per-dst degree (zero-init; re-zeroed by scatter)
__device__ int   g_off[NMAX + 1];          // CSR offsets
__device__ int   g_pos[NMAX];              // scatter cursors
__device__ int2  g_edge[EMAX];             // dst-grouped {src, val_bits}
__device__ int   g_part[512];              // scan partials

// ---------------- 0) split W into bf16 hi/lo ----------------
__global__ void w_split_kernel(const float* __restrict__ W)
{
    int i = blockIdx.x * blockDim.x + threadIdx.x;
    if (i < FT * FT) {
        float w = W[i];
        __nv_bfloat16 hi = __float2bfloat16(w);
        float lo = w - __bfloat162float(hi);
        g_Whi[i] = hi;
        g_Wlo[i] = __float2bfloat16(lo);
    }
}

// ---------------- 1) GEMM: fts = seq @ W^T via WMMA bf16-split -------------
// (exact round-8 structure — the known-good 236us configuration)
// block = 256 threads (8 warps), 64 rows x 128 cols per block.
// smem: A tile hi/lo bf16 [64][128] each = 32KB.
// Warp w: rows [(w&3)*16, +16), cols [(w>>2)*64, +64) = 4 acc tiles of 16x16.
// D = Ah*Bh + Ah*Bl + Al*Bh, fp32 accum (AlBl dropped, ~2^-18 rel).
__global__ void __launch_bounds__(256)
gemm_wmma_kernel(const float* __restrict__ seq, int n)
{
    __shared__ __nv_bfloat16 Ahi[64 * FT];
    __shared__ __nv_bfloat16 Alo[64 * FT];

    const int tid = threadIdx.x;
    const int wid = tid >> 5;
    const int rowBase = blockIdx.x * 64;

    // convert 64 seq rows to bf16 hi/lo in smem (2048 float4, 8 per thread)
    for (int i = tid; i < 64 * 32; i += 256) {
        int row = i >> 5;
        int c4  = i & 31;
        float4 v = make_float4(0.f, 0.f, 0.f, 0.f);
        int grow = rowBase + row;
        if (grow < n)
            v = ((const float4*)(seq + (size_t)grow * FT))[c4];
        __nv_bfloat16 h0 = __float2bfloat16(v.x);
        __nv_bfloat16 h1 = __float2bfloat16(v.y);
        __nv_bfloat16 h2 = __float2bfloat16(v.z);
        __nv_bfloat16 h3 = __float2bfloat16(v.w);
        __nv_bfloat162* dh = (__nv_bfloat162*)(Ahi + row * FT + c4 * 4);
        dh[0] = __nv_bfloat162(h0, h1);
        dh[1] = __nv_bfloat162(h2, h3);
        __nv_bfloat162* dl = (__nv_bfloat162*)(Alo + row * FT + c4 * 4);
        dl[0] = __nv_bfloat162(__float2bfloat16(v.x - __bfloat162float(h0)),
                               __float2bfloat16(v.y - __bfloat162float(h1)));
        dl[1] = __nv_bfloat162(__float2bfloat16(v.z - __bfloat162float(h2)),
                               __float2bfloat16(v.w - __bfloat162float(h3)));
    }
    __syncthreads();

    const int mrow    = (wid & 3) * 16;
    const int colBase = (wid >> 2) * 64;

    wmma::fragment<wmma::accumulator, 16, 16, 16, float> acc[4];
#pragma unroll
    for (int ct = 0; ct < 4; ct++) wmma::fill_fragment(acc[ct], 0.0f);

#pragma unroll
    for (int kt = 0; kt < 8; kt++) {
        const int k = kt * 16;
        wmma::fragment<wmma::matrix_a, 16, 16, 16, __nv_bfloat16, wmma::row_major> ah, al;
        wmma::load_matrix_sync(ah, Ahi + mrow * FT + k, FT);
        wmma::load_matrix_sync(al, Alo + mrow * FT + k, FT);
#pragma unroll
        for (int ct = 0; ct < 4; ct++) {
            const int col = colBase + ct * 16;
            wmma::fragment<wmma::matrix_b, 16, 16, 16, __nv_bfloat16, wmma::col_major> bh, bl;
            wmma::load_matrix_sync(bh, g_Whi + (size_t)col * FT + k, FT);
            wmma::load_matrix_sync(bl, g_Wlo + (size_t)col * FT + k, FT);
            wmma::mma_sync(acc[ct], ah, bh, acc[ct]);
            wmma::mma_sync(acc[ct], ah, bl, acc[ct]);
            wmma::mma_sync(acc[ct], al, bh, acc[ct]);
        }
    }

#pragma unroll
    for (int ct = 0; ct < 4; ct++) {
        float* dst = g_fts + (size_t)(rowBase + mrow) * FT + colBase + ct * 16;
        wmma::store_matrix_sync(dst, acc[ct], FT, wmma::mem_row_major);
    }
}

// ---------------- 2) histogram of dst (4 edges/thread, vector loads) -------
__global__ void hist_kernel(const int* __restrict__ dst, int e)
{
    int i4 = (blockIdx.x * blockDim.x + threadIdx.x) * 4;
    if (i4 + 3 < e) {
        int4 d = *(const int4*)(dst + i4);
        atomicAdd(&g_deg[d.x], 1);
        atomicAdd(&g_deg[d.y], 1);
        atomicAdd(&g_deg[d.z], 1);
        atomicAdd(&g_deg[d.w], 1);
    } else {
        for (int i = i4; i < e; i++) atomicAdd(&g_deg[dst[i]], 1);
    }
}

// ---------------- 3) scan: per-chunk partial sums ----------------
__global__ void scan_partials(int n)
{
    __shared__ int s[256];
    int i = blockIdx.x * 256 + threadIdx.x;
    int v = (i < n) ? g_deg[i] : 0;
    s[threadIdx.x] = v;
    __syncthreads();
    for (int d = 128; d > 0; d >>= 1) {
        if (threadIdx.x < d) s[threadIdx.x] += s[threadIdx.x + d];
        __syncthreads();
    }
    if (threadIdx.x == 0) g_part[blockIdx.x] = s[0];
}

// ---------------- 4) scan: write offsets (computes own chunk prefix) -------
__global__ void scan_write(int n, int nchunks)
{
    __shared__ int s[256];
    __shared__ int base_sh;
    const int t = threadIdx.x;
    const int b = blockIdx.x;

    {
        int acc = 0;
        for (int c = t; c < b; c += 256) acc += g_part[c];
        s[t] = acc;
        __syncthreads();
        for (int d = 128; d > 0; d >>= 1) {
            if (t < d) s[t] += s[t + d];
            __syncthreads();
        }
        if (t == 0) base_sh = s[0];
        __syncthreads();
    }
    const int base = base_sh;
    __syncthreads();

    int i = b * 256 + t;
    int v = (i < n) ? g_deg[i] : 0;
    s[t] = v;
    __syncthreads();
    for (int d = 1; d < 256; d <<= 1) {
        int tmp = (t >= d) ? s[t - d] : 0;
        __syncthreads();
        s[t] += tmp;
        __syncthreads();
    }
    int incl = s[t];
    int excl = incl - v;
    if (i < n) {
        int off = base + excl;
        g_off[i] = off;
        g_pos[i] = off;
    }
    if (b == nchunks - 1 && t == 255)
        g_off[n] = base + incl;
}

// ---------------- 5) scatter (4 edges/thread) + re-zero g_deg --------------
__global__ void scatter_kernel(const int*   __restrict__ dst,
                               const int*   __restrict__ src,
                               const float* __restrict__ val,
                               int e, int n)
{
    int tidg = blockIdx.x * blockDim.x + threadIdx.x;
    int i4 = tidg * 4;
    if (i4 + 3 < e) {
        int4   d = *(const int4*)  (dst + i4);
        int4   s = *(const int4*)  (src + i4);
        float4 v = *(const float4*)(val + i4);
        int p0 = atomicAdd(&g_pos[d.x], 1);
        int p1 = atomicAdd(&g_pos[d.y], 1);
        int p2 = atomicAdd(&g_pos[d.z], 1);
        int p3 = atomicAdd(&g_pos[d.w], 1);
        g_edge[p0] = make_int2(s.x, __float_as_int(v.x));
        g_edge[p1] = make_int2(s.y, __float_as_int(v.y));
        g_edge[p2] = make_int2(s.z, __float_as_int(v.z));
        g_edge[p3] = make_int2(s.w, __float_as_int(v.w));
    } else {
        for (int i = i4; i < e; i++) {
            int idx = atomicAdd(&g_pos[dst[i]], 1);
            g_edge[idx] = make_int2(src[i], __float_as_int(val[i]));
        }
    }
    // g_deg is dead after scan_write; reset 4 entries per thread for the
    // next replay (no separate memset launch).
    if (i4 < n) {
        int lim = min(i4 + 4, n);
        for (int i = i4; i < lim; i++) g_deg[i] = 0;
    }
}

// ---------------- 6) SpMM gather: warp per dst node, no float atomics ------
// unroll 16 for deeper gather MLP against L2-hit latency.
__global__ void spmm_kernel(const float* __restrict__ bias,
                            const float* __restrict__ prelu_a,
                            float* __restrict__ out,
                            int n)
{
    const int warp = (blockIdx.x * blockDim.x + threadIdx.x) >> 5;
    const int lane = threadIdx.x & 31;
    if (warp >= n) return;

    const int off0 = g_off[warp];
    const int off1 = g_off[warp + 1];

    float4 acc = make_float4(0.f, 0.f, 0.f, 0.f);
    const float4* fts4 = (const float4*)g_fts;

    for (int base = off0; base < off1; base += 32) {
        int e = base + lane;
        int   s = 0;
        float v = 0.f;
        if (e < off1) {
            int2 p = __ldcs(&g_edge[e]);   // coalesced 8B read, evict-first
            s = p.x;
            v = __int_as_float(p.y);
        }
        int cnt = min(32, off1 - base);
#pragma unroll 16
        for (int j = 0; j < cnt; j++) {
            int   sj = __shfl_sync(0xffffffffu, s, j);
            float vj = __shfl_sync(0xffffffffu, v, j);
            float4 f = fts4[(size_t)sj * 32 + lane];
            acc.x += vj * f.x;
            acc.y += vj * f.y;
            acc.z += vj * f.z;
            acc.w += vj * f.w;
        }
    }

    float4 b4 = ((const float4*)bias)[lane];
    float  a  = prelu_a[0];
    float4 o;
    o.x = acc.x + b4.x; o.y = acc.y + b4.y;
    o.z = acc.z + b4.z; o.w = acc.w + b4.w;
    o.x = (o.x >= 0.f) ? o.x : a * o.x;
    o.y = (o.y >= 0.f) ? o.y : a * o.y;
    o.z = (o.z >= 0.f) ? o.z : a * o.z;
    o.w = (o.w >= 0.f) ? o.w : a * o.w;
    __stcs((float4*)(out + (size_t)warp * FT) + lane, o);  // evict-first write
}

// ---------------- side-stream handles (created at program load) ------------
struct AuxStreams {
    cudaStream_t s2;
    cudaEvent_t  evFork, evJoin;
    AuxStreams() {
        cudaStreamCreateWithFlags(&s2, cudaStreamNonBlocking);
        cudaEventCreateWithFlags(&evFork, cudaEventDisableTiming);
        cudaEventCreateWithFlags(&evJoin, cudaEventDisableTiming);
    }
};
static AuxStreams g_aux;

// ---------------- launcher ----------------
// Submission order interleaves the two streams so gemm_wmma is the 4th
// kernel submitted (the one ncu profiles), with identical stream/event
// semantics: s2 order hist->partials->write->scatter, default order
// w_split->gemm->spmm, spmm after the join event.
extern "C" void kernel_launch(void* const* d_in, const int* in_sizes, int n_in,
                              void* d_out, int out_size)
{
    const float* seq      = (const float*)d_in[0];
    const float* W        = (const float*)d_in[1];
    const float* bias     = (const float*)d_in[2];
    const float* prelu_a  = (const float*)d_in[3];
    const float* edge_val = (const float*)d_in[4];
    const int*   edge_src = (const int*)  d_in[5];
    const int*   edge_dst = (const int*)  d_in[6];

    const int n = in_sizes[0] / FT;     // 100000
    const int e = in_sizes[4];          // 1600000

    // fork: branch B (CSR build) runs on side stream s2
    cudaEventRecord(g_aux.evFork, 0);
    cudaStreamWaitEvent(g_aux.s2, g_aux.evFork, 0);

    const int e4blocks = (e / 4 + 255) / 256 + 1;
    const int nchunks = (n + 255) / 256;

    // #1 (s2)
    hist_kernel<<<e4blocks, 256, 0, g_aux.s2>>>(edge_dst, e);
    // #2 (default)
    w_split_kernel<<<(FT * FT + 255) / 256, 256>>>(W);
    // #3 (s2)
    scan_partials<<<nchunks, 256, 0, g_aux.s2>>>(n);
    // #4 (default)  <- profiled by ncu
    gemm_wmma_kernel<<<(n + 63) / 64, 256>>>(seq, n);
    // #5 (s2)
    scan_write<<<nchunks, 256, 0, g_aux.s2>>>(n, nchunks);
    // #6 (s2)
    scatter_kernel<<<e4blocks, 256, 0, g_aux.s2>>>(edge_dst, edge_src, edge_val, e, n);
    cudaEventRecord(g_aux.evJoin, g_aux.s2);

    // join, then SpMM (#7)
    cudaStreamWaitEvent(0, g_aux.evJoin, 0);
    const int warps_per_block = 8;
    spmm_kernel<<<(n + warps_per_block - 1) / warps_per_block, warps_per_block * 32>>>(
        bias, prelu_a, (float*)d_out, n);
}

// round 14
// speedup vs baseline: 1.4276x; 1.0104x over previous
#include <cuda_runtime.h>
#include <cuda_bf16.h>
#include <mma.h>
#include <stdint.h>

using namespace nvcuda;

#define NMAX 100000
#define NPAD 100096        // NMAX rounded up to 128 (whole-tile stores at tail)
#define EMAX 1600000
#define FT   128           // in_ft == out_ft == 128

// ---------------- device scratch (allocation-free) ----------------
__device__ float         g_fts[NPAD * FT]; // linear transform result [N,128]
__device__ __nv_bfloat16 g_Whi[FT * FT];   // W hi bf16
__device__ __nv_bfloat16 g_Wlo[FT * FT];   // W residual bf16
__device__ int   g_deg[NMAX];              // per-dst degree (zero-init; re-zeroed by scatter)
__device__ int   g_off[NMAX + 1];          // CSR offsets
__device__ int   g_pos[NMAX];              // scatter cursors
__device__ int2  g_edge[EMAX];             // dst-grouped {src, val_bits}
__device__ int   g_part[512];              // scan partials

// ---------------- 0) split W into bf16 hi/lo ----------------
__global__ void w_split_kernel(const float* __restrict__ W)
{
    int i = blockIdx.x * blockDim.x + threadIdx.x;
    if (i < FT * FT) {
        float w = W[i];
        __nv_bfloat16 hi = __float2bfloat16(w);
        float lo = w - __bfloat162float(hi);
        g_Whi[i] = hi;
        g_Wlo[i] = __float2bfloat16(lo);
    }
}

// ---------------- 1) GEMM: fts = seq @ W^T via WMMA bf16-split -------------
// block = 256 threads (8 warps), 128 rows x 128 cols per block.
// smem (dynamic 64KB): A tile hi/lo bf16 [128][128] each.
// Warp w: rows [(w&3)*32, +32), cols [(w>>2)*64, +64) = 2x4 acc tiles.
// Per kt: 4 A-frag LDS + 8 B-frag LDG + 24 MMAs -> B L1 traffic per MMA
// halved vs the 16x64 variant (the round-13 L1 bottleneck).
// D = Ah*Bh + Ah*Bl + Al*Bh, fp32 accum (AlBl dropped, ~2^-18 rel).
__global__ void __launch_bounds__(256)
gemm_wmma_kernel(const float* __restrict__ seq, int n)
{
    extern __shared__ __nv_bfloat16 smA[];
    __nv_bfloat16* Ahi = smA;                 // 128*128 bf16 = 32KB
    __nv_bfloat16* Alo = smA + 128 * FT;      // 32KB

    const int tid = threadIdx.x;
    const int wid = tid >> 5;
    const int rowBase = blockIdx.x * 128;

    // convert 128 seq rows to bf16 hi/lo in smem (4096 float4, 16 per thread)
    for (int i = tid; i < 128 * 32; i += 256) {
        int row = i >> 5;
        int c4  = i & 31;
        float4 v = make_float4(0.f, 0.f, 0.f, 0.f);
        int grow = rowBase + row;
        if (grow < n)
            v = ((const float4*)(seq + (size_t)grow * FT))[c4];
        __nv_bfloat16 h0 = __float2bfloat16(v.x);
        __nv_bfloat16 h1 = __float2bfloat16(v.y);
        __nv_bfloat16 h2 = __float2bfloat16(v.z);
        __nv_bfloat16 h3 = __float2bfloat16(v.w);
        __nv_bfloat162* dh = (__nv_bfloat162*)(Ahi + row * FT + c4 * 4);
        dh[0] = __nv_bfloat162(h0, h1);
        dh[1] = __nv_bfloat162(h2, h3);
        __nv_bfloat162* dl = (__nv_bfloat162*)(Alo + row * FT + c4 * 4);
        dl[0] = __nv_bfloat162(__float2bfloat16(v.x - __bfloat162float(h0)),
                               __float2bfloat16(v.y - __bfloat162float(h1)));
        dl[1] = __nv_bfloat162(__float2bfloat16(v.z - __bfloat162float(h2)),
                               __float2bfloat16(v.w - __bfloat162float(h3)));
    }
    __syncthreads();

    const int mrow    = (wid & 3) * 32;       // 0,32,64,96
    const int colBase = (wid >> 2) * 64;      // 0 or 64

    wmma::fragment<wmma::accumulator, 16, 16, 16, float> acc[2][4];
#pragma unroll
    for (int mr = 0; mr < 2; mr++)
#pragma unroll
        for (int ct = 0; ct < 4; ct++)
            wmma::fill_fragment(acc[mr][ct], 0.0f);

#pragma unroll
    for (int kt = 0; kt < 8; kt++) {
        const int k = kt * 16;
        wmma::fragment<wmma::matrix_a, 16, 16, 16, __nv_bfloat16, wmma::row_major> ah[2], al[2];
#pragma unroll
        for (int mr = 0; mr < 2; mr++) {
            wmma::load_matrix_sync(ah[mr], Ahi + (mrow + mr * 16) * FT + k, FT);
            wmma::load_matrix_sync(al[mr], Alo + (mrow + mr * 16) * FT + k, FT);
        }
#pragma unroll
        for (int ct = 0; ct < 4; ct++) {
            const int col = colBase + ct * 16;
            wmma::fragment<wmma::matrix_b, 16, 16, 16, __nv_bfloat16, wmma::col_major> bh, bl;
            wmma::load_matrix_sync(bh, g_Whi + (size_t)col * FT + k, FT);
            wmma::load_matrix_sync(bl, g_Wlo + (size_t)col * FT + k, FT);
#pragma unroll
            for (int mr = 0; mr < 2; mr++) {
                wmma::mma_sync(acc[mr][ct], ah[mr], bh, acc[mr][ct]);
                wmma::mma_sync(acc[mr][ct], ah[mr], bl, acc[mr][ct]);
                wmma::mma_sync(acc[mr][ct], al[mr], bh, acc[mr][ct]);
            }
        }
    }

#pragma unroll
    for (int mr = 0; mr < 2; mr++)
#pragma unroll
        for (int ct = 0; ct < 4; ct++) {
            float* dst = g_fts + (size_t)(rowBase + mrow + mr * 16) * FT
                       + colBase + ct * 16;
            wmma::store_matrix_sync(dst, acc[mr][ct], FT, wmma::mem_row_major);
        }
}

// ---------------- 2) histogram of dst (4 edges/thread, vector loads) -------
__global__ void hist_kernel(const int* __restrict__ dst, int e)
{
    int i4 = (blockIdx.x * blockDim.x + threadIdx.x) * 4;
    if (i4 + 3 < e) {
        int4 d = *(const int4*)(dst + i4);
        atomicAdd(&g_deg[d.x], 1);
        atomicAdd(&g_deg[d.y], 1);
        atomicAdd(&g_deg[d.z], 1);
        atomicAdd(&g_deg[d.w], 1);
    } else {
        for (int i = i4; i < e; i++) atomicAdd(&g_deg[dst[i]], 1);
    }
}

// ---------------- 3) scan: per-chunk partial sums ----------------
__global__ void scan_partials(int n)
{
    __shared__ int s[256];
    int i = blockIdx.x * 256 + threadIdx.x;
    int v = (i < n) ? g_deg[i] : 0;
    s[threadIdx.x] = v;
    __syncthreads();
    for (int d = 128; d > 0; d >>= 1) {
        if (threadIdx.x < d) s[threadIdx.x] += s[threadIdx.x + d];
        __syncthreads();
    }
    if (threadIdx.x == 0) g_part[blockIdx.x] = s[0];
}

// ---------------- 4) scan: write offsets (computes own chunk prefix) -------
__global__ void scan_write(int n, int nchunks)
{
    __shared__ int s[256];
    __shared__ int base_sh;
    const int t = threadIdx.x;
    const int b = blockIdx.x;

    {
        int acc = 0;
        for (int c = t; c < b; c += 256) acc += g_part[c];
        s[t] = acc;
        __syncthreads();
        for (int d = 128; d > 0; d >>= 1) {
            if (t < d) s[t] += s[t + d];
            __syncthreads();
        }
        if (t == 0) base_sh = s[0];
        __syncthreads();
    }
    const int base = base_sh;
    __syncthreads();

    int i = b * 256 + t;
    int v = (i < n) ? g_deg[i] : 0;
    s[t] = v;
    __syncthreads();
    for (int d = 1; d < 256; d <<= 1) {
        int tmp = (t >= d) ? s[t - d] : 0;
        __syncthreads();
        s[t] += tmp;
        __syncthreads();
    }
    int incl = s[t];
    int excl = incl - v;
    if (i < n) {
        int off = base + excl;
        g_off[i] = off;
        g_pos[i] = off;
    }
    if (b == nchunks - 1 && t == 255)
        g_off[n] = base + incl;
}

// ---------------- 5) scatter (4 edges/thread) + re-zero g_deg --------------
__global__ void scatter_kernel(const int*   __restrict__ dst,
                               const int*   __restrict__ src,
                               const float* __restrict__ val,
                               int e, int n)
{
    int tidg = blockIdx.x * blockDim.x + threadIdx.x;
    int i4 = tidg * 4;
    if (i4 + 3 < e) {
        int4   d = *(const int4*)  (dst + i4);
        int4   s = *(const int4*)  (src + i4);
        float4 v = *(const float4*)(val + i4);
        int p0 = atomicAdd(&g_pos[d.x], 1);
        int p1 = atomicAdd(&g_pos[d.y], 1);
        int p2 = atomicAdd(&g_pos[d.z], 1);
        int p3 = atomicAdd(&g_pos[d.w], 1);
        g_edge[p0] = make_int2(s.x, __float_as_int(v.x));
        g_edge[p1] = make_int2(s.y, __float_as_int(v.y));
        g_edge[p2] = make_int2(s.z, __float_as_int(v.z));
        g_edge[p3] = make_int2(s.w, __float_as_int(v.w));
    } else {
        for (int i = i4; i < e; i++) {
            int idx = atomicAdd(&g_pos[dst[i]], 1);
            g_edge[idx] = make_int2(src[i], __float_as_int(val[i]));
        }
    }
    // g_deg is dead after scan_write; reset 4 entries per thread for the
    // next replay (no separate memset launch).
    if (i4 < n) {
        int lim = min(i4 + 4, n);
        for (int i = i4; i < lim; i++) g_deg[i] = 0;
    }
}

// ---------------- 6) SpMM gather: warp per dst node, no float atomics ------
__global__ void spmm_kernel(const float* __restrict__ bias,
                            const float* __restrict__ prelu_a,
                            float* __restrict__ out,
                            int n)
{
    const int warp = (blockIdx.x * blockDim.x + threadIdx.x) >> 5;
    const int lane = threadIdx.x & 31;
    if (warp >= n) return;

    const int off0 = g_off[warp];
    const int off1 = g_off[warp + 1];

    float4 acc = make_float4(0.f, 0.f, 0.f, 0.f);
    const float4* fts4 = (const float4*)g_fts;

    for (int base = off0; base < off1; base += 32) {
        int e = base + lane;
        int   s = 0;
        float v = 0.f;
        if (e < off1) {
            int2 p = __ldcs(&g_edge[e]);   // coalesced 8B read, evict-first
            s = p.x;
            v = __int_as_float(p.y);
        }
        int cnt = min(32, off1 - base);
#pragma unroll 16
        for (int j = 0; j < cnt; j++) {
            int   sj = __shfl_sync(0xffffffffu, s, j);
            float vj = __shfl_sync(0xffffffffu, v, j);
            float4 f = fts4[(size_t)sj * 32 + lane];
            acc.x += vj * f.x;
            acc.y += vj * f.y;
            acc.z += vj * f.z;
            acc.w += vj * f.w;
        }
    }

    float4 b4 = ((const float4*)bias)[lane];
    float  a  = prelu_a[0];
    float4 o;
    o.x = acc.x + b4.x; o.y = acc.y + b4.y;
    o.z = acc.z + b4.z; o.w = acc.w + b4.w;
    o.x = (o.x >= 0.f) ? o.x : a * o.x;
    o.y = (o.y >= 0.f) ? o.y : a * o.y;
    o.z = (o.z >= 0.f) ? o.z : a * o.z;
    o.w = (o.w >= 0.f) ? o.w : a * o.w;
    __stcs((float4*)(out + (size_t)warp * FT) + lane, o);  // evict-first write
}

// ---------------- side-stream handles (created at program load) ------------
struct AuxStreams {
    cudaStream_t s2;
    cudaEvent_t  evFork, evJoin;
    AuxStreams() {
        cudaStreamCreateWithFlags(&s2, cudaStreamNonBlocking);
        cudaEventCreateWithFlags(&evFork, cudaEventDisableTiming);
        cudaEventCreateWithFlags(&evJoin, cudaEventDisableTiming);
    }
};
static AuxStreams g_aux;

// ---------------- launcher ----------------
// gemm_wmma stays the 4th kernel submitted (the one ncu profiles).
extern "C" void kernel_launch(void* const* d_in, const int* in_sizes, int n_in,
                              void* d_out, int out_size)
{
    const float* seq      = (const float*)d_in[0];
    const float* W        = (const float*)d_in[1];
    const float* bias     = (const float*)d_in[2];
    const float* prelu_a  = (const float*)d_in[3];
    const float* edge_val = (const float*)d_in[4];
    const int*   edge_src = (const int*)  d_in[5];
    const int*   edge_dst = (const int*)  d_in[6];

    const int n = in_sizes[0] / FT;     // 100000
    const int e = in_sizes[4];          // 1600000

    // fork: branch B (CSR build) runs on side stream s2
    cudaEventRecord(g_aux.evFork, 0);
    cudaStreamWaitEvent(g_aux.s2, g_aux.evFork, 0);

    const int e4blocks = (e / 4 + 255) / 256 + 1;
    const int nchunks = (n + 255) / 256;

    // #1 (s2)
    hist_kernel<<<e4blocks, 256, 0, g_aux.s2>>>(edge_dst, e);
    // #2 (default)
    w_split_kernel<<<(FT * FT + 255) / 256, 256>>>(W);
    // #3 (s2)
    scan_partials<<<nchunks, 256, 0, g_aux.s2>>>(n);
    // #4 (default)  <- profiled by ncu
    const int gemm_smem = 2 * 128 * FT * sizeof(__nv_bfloat16);  // 64KB
    cudaFuncSetAttribute(gemm_wmma_kernel,
                         cudaFuncAttributeMaxDynamicSharedMemorySize, gemm_smem);
    gemm_wmma_kernel<<<(n + 127) / 128, 256, gemm_smem>>>(seq, n);
    // #5 (s2)
    scan_write<<<nchunks, 256, 0, g_aux.s2>>>(n, nchunks);
    // #6 (s2)
    scatter_kernel<<<e4blocks, 256, 0, g_aux.s2>>>(edge_dst, edge_src, edge_val, e, n);
    cudaEventRecord(g_aux.evJoin, g_aux.s2);

    // join, then SpMM (#7)
    cudaStreamWaitEvent(0, g_aux.evJoin, 0);
    const int warps_per_block = 8;
    spmm_kernel<<<(n + warps_per_block - 1) / warps_per_block, warps_per_block * 32>>>(
        bias, prelu_a, (float*)d_out, n);
}

// round 15
// speedup vs baseline: 1.7583x; 1.2317x over previous
#include <cuda_runtime.h>
#include <cuda_bf16.h>
#include <mma.h>
#include <stdint.h>

using namespace nvcuda;

#define NMAX 100000
#define NPAD 100096        // NMAX rounded up to 128 (whole-tile stores at tail)
#define EMAX 1600000
#define FT   128           // in_ft == out_ft == 128
#define LDP  136           // padded smem leading dim (272B stride: conflict-free LDSM)

// ---------------- device scratch (allocation-free) ----------------
__device__ float         g_fts[NPAD * FT]; // linear transform result [N,128]
__device__ __nv_bfloat16 g_Whi[FT * FT];   // W hi bf16
__device__ __nv_bfloat16 g_Wlo[FT * FT];   // W residual bf16
__device__ int   g_deg[NMAX];              // per-dst degree (zero-init; re-zeroed by scatter)
__device__ int   g_off[NMAX + 1];          // CSR offsets
__device__ int   g_pos[NMAX];              // scatter cursors
__device__ int2  g_edge[EMAX];             // dst-grouped {src, val_bits}
__device__ int   g_part[512];              // scan partials

// ---------------- 0) split W into bf16 hi/lo ----------------
__global__ void w_split_kernel(const float* __restrict__ W)
{
    int i = blockIdx.x * blockDim.x + threadIdx.x;
    if (i < FT * FT) {
        float w = W[i];
        __nv_bfloat16 hi = __float2bfloat16(w);
        float lo = w - __bfloat162float(hi);
        g_Whi[i] = hi;
        g_Wlo[i] = __float2bfloat16(lo);
    }
}

// ---------------- 1) GEMM: fts = seq @ W^T via WMMA bf16-split -------------
// R8 tiling (block 64 rows x 128 cols, warp 16x64, 4 acc frags) but BOTH
// operands staged in smem with PADDED ld=136 (272B row stride -> each row of
// an 8x8 ldmatrix group lands on a different bank group; conflict-free LDSM).
// Global-sourced fragment loads (which compile to per-element 2B LDGs) are
// eliminated entirely — that was the invariant bottleneck of R13/R14.
// D = Ah*Bh + Ah*Bl + Al*Bh, fp32 accum (AlBl dropped, ~2^-18 rel).
__global__ void __launch_bounds__(256)
gemm_wmma_kernel(const float* __restrict__ seq, int n)
{
    extern __shared__ __nv_bfloat16 sm[];
    __nv_bfloat16* Whi_s = sm;                    // 128 x LDP
    __nv_bfloat16* Wlo_s = Whi_s + FT * LDP;      // 128 x LDP
    __nv_bfloat16* Ahi   = Wlo_s + FT * LDP;      // 64 x LDP
    __nv_bfloat16* Alo   = Ahi + 64 * LDP;        // 64 x LDP

    const int tid = threadIdx.x;
    const int wid = tid >> 5;
    const int rowBase = blockIdx.x * 64;

    // stage W hi/lo into padded smem (int4 = 8 bf16; 128 rows x 16 int4)
    for (int i = tid; i < FT * 16; i += 256) {
        int row = i >> 4;
        int c8  = i & 15;
        *(int4*)(Whi_s + row * LDP + c8 * 8) = ((const int4*)g_Whi)[i];
        *(int4*)(Wlo_s + row * LDP + c8 * 8) = ((const int4*)g_Wlo)[i];
    }

    // convert 64 seq rows to bf16 hi/lo into padded smem
    for (int i = tid; i < 64 * 32; i += 256) {
        int row = i >> 5;
        int c4  = i & 31;
        float4 v = make_float4(0.f, 0.f, 0.f, 0.f);
        int grow = rowBase + row;
        if (grow < n)
            v = ((const float4*)(seq + (size_t)grow * FT))[c4];
        __nv_bfloat16 h0 = __float2bfloat16(v.x);
        __nv_bfloat16 h1 = __float2bfloat16(v.y);
        __nv_bfloat16 h2 = __float2bfloat16(v.z);
        __nv_bfloat16 h3 = __float2bfloat16(v.w);
        __nv_bfloat162* dh = (__nv_bfloat162*)(Ahi + row * LDP + c4 * 4);
        dh[0] = __nv_bfloat162(h0, h1);
        dh[1] = __nv_bfloat162(h2, h3);
        __nv_bfloat162* dl = (__nv_bfloat162*)(Alo + row * LDP + c4 * 4);
        dl[0] = __nv_bfloat162(__float2bfloat16(v.x - __bfloat162float(h0)),
                               __float2bfloat16(v.y - __bfloat162float(h1)));
        dl[1] = __nv_bfloat162(__float2bfloat16(v.z - __bfloat162float(h2)),
                               __float2bfloat16(v.w - __bfloat162float(h3)));
    }
    __syncthreads();

    const int mrow    = (wid & 3) * 16;
    const int colBase = (wid >> 2) * 64;

    wmma::fragment<wmma::accumulator, 16, 16, 16, float> acc[4];
#pragma unroll
    for (int ct = 0; ct < 4; ct++) wmma::fill_fragment(acc[ct], 0.0f);

#pragma unroll
    for (int kt = 0; kt < 8; kt++) {
        const int k = kt * 16;
        wmma::fragment<wmma::matrix_a, 16, 16, 16, __nv_bfloat16, wmma::row_major> ah, al;
        wmma::load_matrix_sync(ah, Ahi + mrow * LDP + k, LDP);
        wmma::load_matrix_sync(al, Alo + mrow * LDP + k, LDP);
#pragma unroll
        for (int ct = 0; ct < 4; ct++) {
            const int col = colBase + ct * 16;
            wmma::fragment<wmma::matrix_b, 16, 16, 16, __nv_bfloat16, wmma::col_major> bh, bl;
            wmma::load_matrix_sync(bh, Whi_s + (size_t)col * LDP + k, LDP);
            wmma::load_matrix_sync(bl, Wlo_s + (size_t)col * LDP + k, LDP);
            wmma::mma_sync(acc[ct], ah, bh, acc[ct]);
            wmma::mma_sync(acc[ct], ah, bl, acc[ct]);
            wmma::mma_sync(acc[ct], al, bh, acc[ct]);
        }
    }

#pragma unroll
    for (int ct = 0; ct < 4; ct++) {
        float* dst = g_fts + (size_t)(rowBase + mrow) * FT + colBase + ct * 16;
        wmma::store_matrix_sync(dst, acc[ct], FT, wmma::mem_row_major);
    }
}

// ---------------- 2) histogram of dst (4 edges/thread, vector loads) -------
__global__ void hist_kernel(const int* __restrict__ dst, int e)
{
    int i4 = (blockIdx.x * blockDim.x + threadIdx.x) * 4;
    if (i4 + 3 < e) {
        int4 d = *(const int4*)(dst + i4);
        atomicAdd(&g_deg[d.x], 1);
        atomicAdd(&g_deg[d.y], 1);
        atomicAdd(&g_deg[d.z], 1);
        atomicAdd(&g_deg[d.w], 1);
    } else {
        for (int i = i4; i < e; i++) atomicAdd(&g_deg[dst[i]], 1);
    }
}

// ---------------- 3) scan: per-chunk partial sums ----------------
__global__ void scan_partials(int n)
{
    __shared__ int s[256];
    int i = blockIdx.x * 256 + threadIdx.x;
    int v = (i < n) ? g_deg[i] : 0;
    s[threadIdx.x] = v;
    __syncthreads();
    for (int d = 128; d > 0; d >>= 1) {
        if (threadIdx.x < d) s[threadIdx.x] += s[threadIdx.x + d];
        __syncthreads();
    }
    if (threadIdx.x == 0) g_part[blockIdx.x] = s[0];
}

// ---------------- 4) scan: write offsets (computes own chunk prefix) -------
__global__ void scan_write(int n, int nchunks)
{
    __shared__ int s[256];
    __shared__ int base_sh;
    const int t = threadIdx.x;
    const int b = blockIdx.x;

    {
        int acc = 0;
        for (int c = t; c < b; c += 256) acc += g_part[c];
        s[t] = acc;
        __syncthreads();
        for (int d = 128; d > 0; d >>= 1) {
            if (t < d) s[t] += s[t + d];
            __syncthreads();
        }
        if (t == 0) base_sh = s[0];
        __syncthreads();
    }
    const int base = base_sh;
    __syncthreads();

    int i = b * 256 + t;
    int v = (i < n) ? g_deg[i] : 0;
    s[t] = v;
    __syncthreads();
    for (int d = 1; d < 256; d <<= 1) {
        int tmp = (t >= d) ? s[t - d] : 0;
        __syncthreads();
        s[t] += tmp;
        __syncthreads();
    }
    int incl = s[t];
    int excl = incl - v;
    if (i < n) {
        int off = base + excl;
        g_off[i] = off;
        g_pos[i] = off;
    }
    if (b == nchunks - 1 && t == 255)
        g_off[n] = base + incl;
}

// ---------------- 5) scatter (4 edges/thread) + re-zero g_deg --------------
__global__ void scatter_kernel(const int*   __restrict__ dst,
                               const int*   __restrict__ src,
                               const float* __restrict__ val,
                               int e, int n)
{
    int tidg = blockIdx.x * blockDim.x + threadIdx.x;
    int i4 = tidg * 4;
    if (i4 + 3 < e) {
        int4   d = *(const int4*)  (dst + i4);
        int4   s = *(const int4*)  (src + i4);
        float4 v = *(const float4*)(val + i4);
        int p0 = atomicAdd(&g_pos[d.x], 1);
        int p1 = atomicAdd(&g_pos[d.y], 1);
        int p2 = atomicAdd(&g_pos[d.z], 1);
        int p3 = atomicAdd(&g_pos[d.w], 1);
        g_edge[p0] = make_int2(s.x, __float_as_int(v.x));
        g_edge[p1] = make_int2(s.y, __float_as_int(v.y));
        g_edge[p2] = make_int2(s.z, __float_as_int(v.z));
        g_edge[p3] = make_int2(s.w, __float_as_int(v.w));
    } else {
        for (int i = i4; i < e; i++) {
            int idx = atomicAdd(&g_pos[dst[i]], 1);
            g_edge[idx] = make_int2(src[i], __float_as_int(val[i]));
        }
    }
    // g_deg is dead after scan_write; reset 4 entries per thread for the
    // next replay (no separate memset launch).
    if (i4 < n) {
        int lim = min(i4 + 4, n);
        for (int i = i4; i < lim; i++) g_deg[i] = 0;
    }
}

// ---------------- 6) SpMM gather: warp per dst node, no float atomics ------
__global__ void spmm_kernel(const float* __restrict__ bias,
                            const float* __restrict__ prelu_a,
                            float* __restrict__ out,
                            int n)
{
    const int warp = (blockIdx.x * blockDim.x + threadIdx.x) >> 5;
    const int lane = threadIdx.x & 31;
    if (warp >= n) return;

    const int off0 = g_off[warp];
    const int off1 = g_off[warp + 1];

    float4 acc = make_float4(0.f, 0.f, 0.f, 0.f);
    const float4* fts4 = (const float4*)g_fts;

    for (int base = off0; base < off1; base += 32) {
        int e = base + lane;
        int   s = 0;
        float v = 0.f;
        if (e < off1) {
            int2 p = __ldcs(&g_edge[e]);   // coalesced 8B read, evict-first
            s = p.x;
            v = __int_as_float(p.y);
        }
        int cnt = min(32, off1 - base);
#pragma unroll 16
        for (int j = 0; j < cnt; j++) {
            int   sj = __shfl_sync(0xffffffffu, s, j);
            float vj = __shfl_sync(0xffffffffu, v, j);
            float4 f = fts4[(size_t)sj * 32 + lane];
            acc.x += vj * f.x;
            acc.y += vj * f.y;
            acc.z += vj * f.z;
            acc.w += vj * f.w;
        }
    }

    float4 b4 = ((const float4*)bias)[lane];
    float  a  = prelu_a[0];
    float4 o;
    o.x = acc.x + b4.x; o.y = acc.y + b4.y;
    o.z = acc.z + b4.z; o.w = acc.w + b4.w;
    o.x = (o.x >= 0.f) ? o.x : a * o.x;
    o.y = (o.y >= 0.f) ? o.y : a * o.y;
    o.z = (o.z >= 0.f) ? o.z : a * o.z;
    o.w = (o.w >= 0.f) ? o.w : a * o.w;
    __stcs((float4*)(out + (size_t)warp * FT) + lane, o);  // evict-first write
}

// ---------------- side-stream handles (created at program load) ------------
struct AuxStreams {
    cudaStream_t s2;
    cudaEvent_t  evFork, evJoin;
    AuxStreams() {
        cudaStreamCreateWithFlags(&s2, cudaStreamNonBlocking);
        cudaEventCreateWithFlags(&evFork, cudaEventDisableTiming);
        cudaEventCreateWithFlags(&evJoin, cudaEventDisableTiming);
    }
};
static AuxStreams g_aux;

// ---------------- launcher ----------------
// gemm_wmma stays the 4th kernel submitted (the one ncu profiles).
extern "C" void kernel_launch(void* const* d_in, const int* in_sizes, int n_in,
                              void* d_out, int out_size)
{
    const float* seq      = (const float*)d_in[0];
    const float* W        = (const float*)d_in[1];
    const float* bias     = (const float*)d_in[2];
    const float* prelu_a  = (const float*)d_in[3];
    const float* edge_val = (const float*)d_in[4];
    const int*   edge_src = (const int*)  d_in[5];
    const int*   edge_dst = (const int*)  d_in[6];

    const int n = in_sizes[0] / FT;     // 100000
    const int e = in_sizes[4];          // 1600000

    // fork: branch B (CSR build) runs on side stream s2
    cudaEventRecord(g_aux.evFork, 0);
    cudaStreamWaitEvent(g_aux.s2, g_aux.evFork, 0);

    const int e4blocks = (e / 4 + 255) / 256 + 1;
    const int nchunks = (n + 255) / 256;

    // #1 (s2)
    hist_kernel<<<e4blocks, 256, 0, g_aux.s2>>>(edge_dst, e);
    // #2 (default)
    w_split_kernel<<<(FT * FT + 255) / 256, 256>>>(W);
    // #3 (s2)
    scan_partials<<<nchunks, 256, 0, g_aux.s2>>>(n);
    // #4 (default)  <- profiled by ncu
    const int gemm_smem = (2 * FT * LDP + 2 * 64 * LDP) * sizeof(__nv_bfloat16); // ~102KB
    cudaFuncSetAttribute(gemm_wmma_kernel,
                         cudaFuncAttributeMaxDynamicSharedMemorySize, gemm_smem);
    gemm_wmma_kernel<<<(n + 63) / 64, 256, gemm_smem>>>(seq, n);
    // #5 (s2)
    scan_write<<<nchunks, 256, 0, g_aux.s2>>>(n, nchunks);
    // #6 (s2)
    scatter_kernel<<<e4blocks, 256, 0, g_aux.s2>>>(edge_dst, edge_src, edge_val, e, n);
    cudaEventRecord(g_aux.evJoin, g_aux.s2);

    // join, then SpMM (#7)
    cudaStreamWaitEvent(0, g_aux.evJoin, 0);
    const int warps_per_block = 8;
    spmm_kernel<<<(n + warps_per_block - 1) / warps_per_block, warps_per_block * 32>>>(
        bias, prelu_a, (float*)d_out, n);
}